// round 11
// baseline (speedup 1.0000x reference)
#include <cuda_runtime.h>
#include <cuda_fp16.h>
#include <cstdint>
#include <math.h>

#define T_TOK   8192
#define DMODEL  512
#define FF      2048
#define NE      8
#define TOPK    2

#define BM 128
#define BN 256
#define ROWS_MAX (TOPK*T_TOK + NE*BM)   // 17408
#define RTILES   (ROWS_MAX / BM)        // 136

// ---------------- static device scratch -------------------------------------
__device__ __half g_hidden[(size_t)ROWS_MAX * FF];    // [136][32][8192h]
__device__ float  g_eout[(size_t)ROWS_MAX * DMODEL];  // row-major fp32
__device__ __half g_xg[(size_t)ROWS_MAX * DMODEL];    // [136][8][8192h]
__device__ __half g_w1t[(size_t)NE * FF * DMODEL];    // tiled
__device__ __half g_w2t[(size_t)NE * DMODEL * FF];    // tiled
__device__ int   g_row_tok[ROWS_MAX];
__device__ int   g_tok_e[T_TOK * TOPK];
__device__ int   g_tok_slot[T_TOK * TOPK];
__device__ float g_tok_w[T_TOK * TOPK];
__device__ int   g_cnt[NE];
__device__ int   g_cur[NE];
__device__ int   g_pofs[NE + 1];

// ---------------- helpers ---------------------------------------------------
__device__ __forceinline__ uint32_t smem_u32(const void* p) {
    uint32_t a;
    asm("{ .reg .u64 t; cvta.to.shared.u64 t, %1; cvt.u32.u64 %0, t; }" : "=r"(a) : "l"(p));
    return a;
}
__device__ __forceinline__ void ldsm_x4(uint32_t& r0, uint32_t& r1, uint32_t& r2, uint32_t& r3,
                                        uint32_t addr) {
    asm volatile("ldmatrix.sync.aligned.m8n8.x4.shared.b16 {%0,%1,%2,%3}, [%4];"
                 : "=r"(r0), "=r"(r1), "=r"(r2), "=r"(r3) : "r"(addr));
}
__device__ __forceinline__ void mma_f16(float& c0, float& c1, float& c2, float& c3,
                                        uint32_t a0, uint32_t a1, uint32_t a2, uint32_t a3,
                                        uint32_t b0, uint32_t b1) {
    asm volatile(
        "mma.sync.aligned.m16n8k16.row.col.f32.f16.f16.f32 "
        "{%0,%1,%2,%3}, {%4,%5,%6,%7}, {%8,%9}, {%0,%1,%2,%3};"
        : "+f"(c0), "+f"(c1), "+f"(c2), "+f"(c3)
        : "r"(a0), "r"(a1), "r"(a2), "r"(a3), "r"(b0), "r"(b1));
}
#define MBARRIER_INIT(addr, cnt) \
    asm volatile("mbarrier.init.shared.b64 [%0], %1;" :: "r"(addr), "r"(cnt) : "memory")
#define MBARRIER_ARRIVE(addr) \
    asm volatile("mbarrier.arrive.shared.b64 _, [%0];" :: "r"(addr) : "memory")
__device__ __forceinline__ void mbar_expect(uint32_t mbar, uint32_t bytes) {
    asm volatile("mbarrier.arrive.expect_tx.shared.b64 _, [%0], %1;"
                 :: "r"(mbar), "r"(bytes) : "memory");
}
__device__ __forceinline__ void bulk_g2s(uint32_t dst, const void* src, uint32_t bytes,
                                         uint32_t mbar) {
    asm volatile("cp.async.bulk.shared::cta.global.mbarrier::complete_tx::bytes "
                 "[%0], [%1], %2, [%3];"
                 :: "r"(dst), "l"(src), "r"(bytes), "r"(mbar) : "memory");
}
__device__ __forceinline__ void mbar_wait(uint32_t mbar, uint32_t parity) {
    uint32_t done;
    asm volatile(
        "{ .reg .pred p; mbarrier.try_wait.parity.acquire.cta.shared::cta.b64 p, [%1], %2; selp.b32 %0, 1, 0, p; }"
        : "=r"(done) : "r"(mbar), "r"(parity) : "memory");
    if (!done) {
        asm volatile(
            "{ .reg .pred P1;\n"
            "WAIT_LOOP_%=:\n"
            "mbarrier.try_wait.parity.acquire.cta.shared::cta.b64 P1, [%0], %1, 0x989680;\n"
            "@P1 bra.uni WAIT_DONE_%=;\n"
            "bra.uni WAIT_LOOP_%=;\n"
            "WAIT_DONE_%=:\n}"
            :: "r"(mbar), "r"(parity) : "memory");
    }
}

// ---------------- init ------------------------------------------------------
__global__ void init_kernel() {
    int i = blockIdx.x * blockDim.x + threadIdx.x;
    if (i < NE) { g_cnt[i] = 0; g_cur[i] = 0; }
    if (i < ROWS_MAX) g_row_tok[i] = 0;
}

// ---------------- router ----------------------------------------------------
__global__ void router_kernel(const float* __restrict__ x,
                              const float* __restrict__ rw,
                              const float* __restrict__ rb) {
    int gtid = blockIdx.x * blockDim.x + threadIdx.x;
    int t = gtid >> 5, lane = gtid & 31;
    if (t >= T_TOK) return;
    const float* xr = x + (size_t)t * DMODEL;
    float acc[NE];
#pragma unroll
    for (int e = 0; e < NE; e++) acc[e] = 0.f;
    for (int d = lane; d < DMODEL; d += 32) {
        float xv = xr[d];
        const float* r = rw + d * NE;
#pragma unroll
        for (int e = 0; e < NE; e++) acc[e] = fmaf(xv, r[e], acc[e]);
    }
#pragma unroll
    for (int off = 16; off > 0; off >>= 1)
#pragma unroll
        for (int e = 0; e < NE; e++)
            acc[e] += __shfl_down_sync(0xffffffffu, acc[e], off);
    if (lane == 0) {
        float best = -1e30f, second = -1e30f;
        int b0 = 0, b1 = 0;
#pragma unroll
        for (int e = 0; e < NE; e++) {
            float l = acc[e] + rb[e];
            if (l > best)        { second = best; b1 = b0; best = l; b0 = e; }
            else if (l > second) { second = l; b1 = e; }
        }
        float w0 = 1.f / (1.f + __expf(second - best));
        g_tok_e[2*t+0] = b0;  g_tok_w[2*t+0] = w0;
        g_tok_e[2*t+1] = b1;  g_tok_w[2*t+1] = 1.f - w0;
        atomicAdd(&g_cnt[b0], 1);
        atomicAdd(&g_cnt[b1], 1);
    }
}

// ---------------- offsets ---------------------------------------------------
__global__ void offsets_kernel() {
    int o = 0;
    for (int e = 0; e < NE; e++) {
        g_pofs[e] = o;
        o += ((g_cnt[e] + BM - 1) / BM) * BM;
    }
    g_pofs[NE] = o;
}

// ---------------- scatter ---------------------------------------------------
__global__ void scatter_kernel() {
    int t = blockIdx.x * blockDim.x + threadIdx.x;
    if (t >= T_TOK) return;
#pragma unroll
    for (int k = 0; k < TOPK; k++) {
        int e = g_tok_e[2*t+k];
        int pos = g_pofs[e] + atomicAdd(&g_cur[e], 1);
        g_row_tok[pos] = t;
        g_tok_slot[2*t+k] = pos;
    }
}

// ---------------- gather x -> fp16 tiled-swizzled ---------------------------
__global__ void gather_h_kernel(const float* __restrict__ x) {
    int id = blockIdx.x * blockDim.x + threadIdx.x;
    const int UNITS = DMODEL / 8;                      // 64
    if (id >= ROWS_MAX * UNITS) return;
    int s  = id / UNITS;
    int un = id % UNITS;
    int kch = un >> 3;
    int u   = un & 7;
    int r   = s & (BM - 1);
    int tok = g_row_tok[s];
    const float4* src = (const float4*)(x + (size_t)tok * DMODEL + un * 8);
    float4 v0 = src[0], v1 = src[1];
    __half2 h[4];
    h[0] = __floats2half2_rn(v0.x, v0.y);
    h[1] = __floats2half2_rn(v0.z, v0.w);
    h[2] = __floats2half2_rn(v1.x, v1.y);
    h[3] = __floats2half2_rn(v1.z, v1.w);
    size_t base = ((size_t)(s >> 7) * (DMODEL / 64) + kch) * 8192;
    *(uint4*)((__half*)g_xg + base + r * 64 + ((u ^ (r & 7)) << 3)) = *(uint4*)h;
}

// ---------------- weight transpose -> fp16 tiled-swizzled -------------------
__global__ void transpose_h_kernel(const float* __restrict__ src, __half* __restrict__ dst,
                                   int R, int C) {
    __shared__ float tile[32][33];
    int e = blockIdx.z;
    int c0 = blockIdx.x * 32, r0 = blockIdx.y * 32;   // c=n, r=k
    const float* s = src + (size_t)e * R * C;
    for (int kk = threadIdx.y; kk < 32; kk += 4)
        tile[kk][threadIdx.x] = s[(size_t)(r0 + kk) * C + c0 + threadIdx.x];
    __syncthreads();
    int n  = c0 + threadIdx.x;
    int kg = threadIdx.y;
    int kbase = r0 + kg * 8;
    __half2 h[4];
#pragma unroll
    for (int j = 0; j < 4; j++)
        h[j] = __floats2half2_rn(tile[kg * 8 + 2*j][threadIdx.x],
                                 tile[kg * 8 + 2*j + 1][threadIdx.x]);
    int nn = n & 255;
    int u  = (kbase & 63) >> 3;
    size_t base = (((size_t)e * (C >> 8) + (n >> 8)) * (R >> 6) + (kbase >> 6)) * 16384;
    *(uint4*)(dst + base + nn * 64 + ((u ^ (nn & 7)) << 3)) = *(uint4*)h;
}

// ---------------- grouped fp16 mma.sync GEMM --------------------------------
// 4-stage bulk pipeline with full/empty mbarrier recycling (no per-iter BAR).
#define A_STAGE 16384
#define B_STAGE 32768
#define STAGE_BYTES (A_STAGE + B_STAGE)            // 49152
#define NSTAGE 4
#define SM_MB (NSTAGE * STAGE_BYTES)               // 196608  (full at +16s, empty at +16s+8)
#define SMEM_TOTAL (SM_MB + 128)

template<int KD, int NTOT, bool TILED_OUT>
__global__ __launch_bounds__(256, 1)
void ffn_mma(const __half* __restrict__ Atiled,
             const __half* __restrict__ Wt,
             const float* __restrict__ bias,
             void* __restrict__ OutV) {
    extern __shared__ __align__(128) char smem[];
    const int tid  = threadIdx.x;
    const int wid  = tid >> 5;
    const int lane = tid & 31;
    const int qid  = lane >> 2;
    const int rid  = lane & 3;
    const int wm   = wid >> 2;
    const int wn   = wid & 3;

    const int r0 = blockIdx.x * BM;
    if (r0 >= g_pofs[NE]) return;
    int e = 0;
    while (r0 >= g_pofs[e + 1]) e++;

    const uint32_t sb = smem_u32(smem);
    if (tid == 0) {
#pragma unroll
        for (int s = 0; s < NSTAGE; s++) {
            MBARRIER_INIT(sb + SM_MB + 16 * s, 1);       // full (tx-based)
            MBARRIER_INIT(sb + SM_MB + 16 * s + 8, 8);   // empty (one arrive/warp)
        }
    }
    __syncthreads();

    const int NCH = KD / 64;
    const __half* Asrc = Atiled + (size_t)blockIdx.x * NCH * 8192;
    const __half* Bsrc = Wt + (((size_t)e * (NTOT / 256) + blockIdx.y) * NCH) * 16384;
    const int n0 = blockIdx.y * BN;

    const int sel = lane >> 3, lr = lane & 7;
    uint32_t a_base[4], a_s7[4];
#pragma unroll
    for (int mt = 0; mt < 4; mt++) {
        int arow = wm * 64 + mt * 16 + (sel & 1) * 8 + lr;
        a_base[mt] = (uint32_t)(arow * 128);
        a_s7[mt]   = (uint32_t)(arow & 7);
    }
    const uint32_t ua0 = (uint32_t)(sel >> 1);
    uint32_t b_base[4], b_s7[4];
#pragma unroll
    for (int g = 0; g < 4; g++) {
        int brow = wn * 64 + (2 * g + (sel >> 1)) * 8 + lr;
        b_base[g] = (uint32_t)(A_STAGE + brow * 128);
        b_s7[g]   = (uint32_t)(brow & 7);
    }
    const uint32_t ub0 = (uint32_t)(sel & 1);

    float acc[4][8][4];
#pragma unroll
    for (int i = 0; i < 4; i++)
#pragma unroll
        for (int j = 0; j < 8; j++)
#pragma unroll
            for (int k = 0; k < 4; k++) acc[i][j][k] = 0.f;

    const int NIT = NCH;
    const int PRO = (NIT < NSTAGE - 1) ? NIT : NSTAGE - 1;   // 3 in-flight

    if (tid == 0) {
        for (int s = 0; s < PRO; s++) {
            mbar_expect(sb + SM_MB + 16 * s, STAGE_BYTES);
            bulk_g2s(sb + s * STAGE_BYTES,           Asrc + (size_t)s * 8192,  A_STAGE,
                     sb + SM_MB + 16 * s);
            bulk_g2s(sb + s * STAGE_BYTES + A_STAGE, Bsrc + (size_t)s * 16384, B_STAGE,
                     sb + SM_MB + 16 * s);
        }
    }

    for (int it = 0; it < NIT; it++) {
        int stage = it % NSTAGE;
        if (it + PRO < NIT && tid == 0) {
            int i2 = it + PRO;
            int s2 = i2 % NSTAGE;
            int r2 = i2 / NSTAGE;
            if (r2 >= 1)   // stage reuse: wait until all 8 warps consumed round r2-1
                mbar_wait(sb + SM_MB + 16 * s2 + 8, (r2 - 1) & 1);
            mbar_expect(sb + SM_MB + 16 * s2, STAGE_BYTES);
            bulk_g2s(sb + s2 * STAGE_BYTES,           Asrc + (size_t)i2 * 8192,  A_STAGE,
                     sb + SM_MB + 16 * s2);
            bulk_g2s(sb + s2 * STAGE_BYTES + A_STAGE, Bsrc + (size_t)i2 * 16384, B_STAGE,
                     sb + SM_MB + 16 * s2);
        }
        mbar_wait(sb + SM_MB + 16 * stage, (it / NSTAGE) & 1);

        const uint32_t sbS = sb + stage * STAGE_BYTES;
#pragma unroll
        for (int ks = 0; ks < 4; ks++) {
            uint32_t a[4][4], b[8][2];
#pragma unroll
            for (int mt = 0; mt < 4; mt++)
                ldsm_x4(a[mt][0], a[mt][1], a[mt][2], a[mt][3],
                        sbS + a_base[mt] + (((ua0 + 2 * ks) ^ a_s7[mt]) << 4));
#pragma unroll
            for (int g = 0; g < 4; g++)
                ldsm_x4(b[2*g][0], b[2*g][1], b[2*g+1][0], b[2*g+1][1],
                        sbS + b_base[g] + (((ub0 + 2 * ks) ^ b_s7[g]) << 4));
#pragma unroll
            for (int mt = 0; mt < 4; mt++)
#pragma unroll
                for (int nt = 0; nt < 8; nt++)
                    mma_f16(acc[mt][nt][0], acc[mt][nt][1], acc[mt][nt][2], acc[mt][nt][3],
                            a[mt][0], a[mt][1], a[mt][2], a[mt][3],
                            b[nt][0], b[nt][1]);
        }
        // warp done reading this stage (ldmatrix is warp-collective)
        if (lane == 0) MBARRIER_ARRIVE(sb + SM_MB + 16 * stage + 8);
    }
    __syncthreads();   // all warps out of the mainloop; stage smem is now free

    const float* be = bias + (size_t)e * NTOT + n0;
    if (TILED_OUT) {
        // stage the 128x256 fp16 tile in smem in exact gmem-tiled-swizzled order,
        // then do a fully coalesced linear copy.
        __half* st = (__half*)smem;
#pragma unroll
        for (int mt = 0; mt < 4; mt++) {
            int r0l = wm * 64 + mt * 16 + qid;
            int r1l = r0l + 8;
#pragma unroll
            for (int nt = 0; nt < 8; nt++) {
                int col = wn * 64 + nt * 8 + 2 * rid;
                float2 bv = *(const float2*)(be + col);
                __half2 h0 = __floats2half2_rn(fmaxf(acc[mt][nt][0] + bv.x, 0.f),
                                               fmaxf(acc[mt][nt][1] + bv.y, 0.f));
                __half2 h1 = __floats2half2_rn(fmaxf(acc[mt][nt][2] + bv.x, 0.f),
                                               fmaxf(acc[mt][nt][3] + bv.y, 0.f));
                // c = wn (chunk of 64 cols), u = nt, off = 2*rid
                int base_c = wn * 8192;
                *(__half2*)(st + base_c + r0l * 64 + ((nt ^ (r0l & 7)) << 3) + 2 * rid) = h0;
                *(__half2*)(st + base_c + r1l * 64 + ((nt ^ (r1l & 7)) << 3) + 2 * rid) = h1;
            }
        }
        __syncthreads();
        __half* Out = (__half*)OutV;
        size_t gbase = ((size_t)blockIdx.x * (NTOT >> 6) + (n0 >> 6)) * 8192;
        uint4* gdst = (uint4*)(Out + gbase);
        const uint4* ssrc = (const uint4*)st;
#pragma unroll
        for (int i = 0; i < 16; i++)
            gdst[tid + i * 256] = ssrc[tid + i * 256];
    } else {
#pragma unroll
        for (int mt = 0; mt < 4; mt++) {
            int rowl = wm * 64 + mt * 16 + qid;
#pragma unroll
            for (int nt = 0; nt < 8; nt++) {
                int col = wn * 64 + nt * 8 + 2 * rid;
                float2 bv = *(const float2*)(be + col);
                float2 v0, v1;
                v0.x = acc[mt][nt][0] + bv.x;
                v0.y = acc[mt][nt][1] + bv.y;
                v1.x = acc[mt][nt][2] + bv.x;
                v1.y = acc[mt][nt][3] + bv.y;
                float* Out = (float*)OutV;
                int row = r0 + rowl;
                *(float2*)(Out + (size_t)row * NTOT + n0 + col)       = v0;
                *(float2*)(Out + (size_t)(row + 8) * NTOT + n0 + col) = v1;
            }
        }
    }
}

// ---------------- combine ---------------------------------------------------
__global__ void combine_kernel(float* __restrict__ out) {
    int gid = blockIdx.x * blockDim.x + threadIdx.x;
    int t = gid >> 7;
    int j = (gid & 127) * 4;
    if (t >= T_TOK) return;
    int s0 = g_tok_slot[2*t], s1 = g_tok_slot[2*t+1];
    float w0 = g_tok_w[2*t], w1 = g_tok_w[2*t+1];
    float4 a = *(const float4*)(g_eout + (size_t)s0 * DMODEL + j);
    float4 b = *(const float4*)(g_eout + (size_t)s1 * DMODEL + j);
    float4 o;
    o.x = w0 * a.x + w1 * b.x;
    o.y = w0 * a.y + w1 * b.y;
    o.z = w0 * a.z + w1 * b.z;
    o.w = w0 * a.w + w1 * b.w;
    *(float4*)(out + (size_t)t * DMODEL + j) = o;
}

// ---------------------------------------------------------------------------
extern "C" void kernel_launch(void* const* d_in, const int* in_sizes, int n_in,
                              void* d_out, int out_size) {
    const float* x        = (const float*)d_in[0];
    const float* router_w = (const float*)d_in[1];
    const float* router_b = (const float*)d_in[2];
    const float* w1       = (const float*)d_in[3];
    const float* b1       = (const float*)d_in[4];
    const float* w2       = (const float*)d_in[5];
    const float* b2       = (const float*)d_in[6];
    float* out            = (float*)d_out;
    (void)in_sizes; (void)n_in; (void)out_size;

    __half* hid; cudaGetSymbolAddress((void**)&hid, g_hidden);
    float*  eo;  cudaGetSymbolAddress((void**)&eo,  g_eout);
    __half* xg;  cudaGetSymbolAddress((void**)&xg,  g_xg);
    __half* w1t; cudaGetSymbolAddress((void**)&w1t, g_w1t);
    __half* w2t; cudaGetSymbolAddress((void**)&w2t, g_w2t);

    cudaFuncSetAttribute(ffn_mma<DMODEL, FF, true >,
                         cudaFuncAttributeMaxDynamicSharedMemorySize, SMEM_TOTAL);
    cudaFuncSetAttribute(ffn_mma<FF, DMODEL, false>,
                         cudaFuncAttributeMaxDynamicSharedMemorySize, SMEM_TOTAL);

    init_kernel<<<(ROWS_MAX + 255) / 256, 256>>>();
    router_kernel<<<(T_TOK * 32 + 255) / 256, 256>>>(x, router_w, router_b);
    offsets_kernel<<<1, 1>>>();
    scatter_kernel<<<(T_TOK + 255) / 256, 256>>>();

    gather_h_kernel<<<(ROWS_MAX * (DMODEL / 8) + 255) / 256, 256>>>(x);
    transpose_h_kernel<<<dim3(FF/32, DMODEL/32, NE), dim3(32, 4)>>>(w1, w1t, DMODEL, FF);
    transpose_h_kernel<<<dim3(DMODEL/32, FF/32, NE), dim3(32, 4)>>>(w2, w2t, FF, DMODEL);

    dim3 g1(RTILES, FF / BN);       // 136 x 8
    ffn_mma<DMODEL, FF, true><<<g1, 256, SMEM_TOTAL>>>(xg, w1t, b1, hid);

    dim3 g2(RTILES, DMODEL / BN);   // 136 x 2
    ffn_mma<FF, DMODEL, false><<<g2, 256, SMEM_TOTAL>>>(hid, w2t, b2, eo);

    combine_kernel<<<(T_TOK * 128 + 255) / 256, 256>>>(out);
}

// round 12
// speedup vs baseline: 1.4015x; 1.4015x over previous
#include <cuda_runtime.h>
#include <cuda_fp16.h>
#include <cstdint>
#include <math.h>

#define T_TOK   8192
#define DMODEL  512
#define FF      2048
#define NE      8
#define TOPK    2

#define BM 128
#define BN 256
#define ROWS_MAX (TOPK*T_TOK + NE*BM)   // 17408
#define RTILES   (ROWS_MAX / BM)        // 136

// ---------------- static device scratch -------------------------------------
__device__ __half g_hidden[(size_t)ROWS_MAX * FF];    // [136][32][8192h]
__device__ float  g_eout[(size_t)ROWS_MAX * DMODEL];  // row-major fp32
__device__ __half g_xg[(size_t)ROWS_MAX * DMODEL];    // [136][8][8192h]
__device__ __half g_w1t[(size_t)NE * FF * DMODEL];    // tiled
__device__ __half g_w2t[(size_t)NE * DMODEL * FF];    // tiled
__device__ int   g_row_tok[ROWS_MAX];
__device__ int   g_tok_e[T_TOK * TOPK];
__device__ int   g_tok_slot[T_TOK * TOPK];
__device__ float g_tok_w[T_TOK * TOPK];
__device__ int   g_cnt[NE];
__device__ int   g_cur[NE];
__device__ int   g_pofs[NE + 1];

// ---------------- helpers ---------------------------------------------------
__device__ __forceinline__ uint32_t smem_u32(const void* p) {
    uint32_t a;
    asm("{ .reg .u64 t; cvta.to.shared.u64 t, %1; cvt.u32.u64 %0, t; }" : "=r"(a) : "l"(p));
    return a;
}
__device__ __forceinline__ void ldsm_x4(uint32_t& r0, uint32_t& r1, uint32_t& r2, uint32_t& r3,
                                        uint32_t addr) {
    asm volatile("ldmatrix.sync.aligned.m8n8.x4.shared.b16 {%0,%1,%2,%3}, [%4];"
                 : "=r"(r0), "=r"(r1), "=r"(r2), "=r"(r3) : "r"(addr));
}
__device__ __forceinline__ void mma_f16(float& c0, float& c1, float& c2, float& c3,
                                        uint32_t a0, uint32_t a1, uint32_t a2, uint32_t a3,
                                        uint32_t b0, uint32_t b1) {
    asm volatile(
        "mma.sync.aligned.m16n8k16.row.col.f32.f16.f16.f32 "
        "{%0,%1,%2,%3}, {%4,%5,%6,%7}, {%8,%9}, {%0,%1,%2,%3};"
        : "+f"(c0), "+f"(c1), "+f"(c2), "+f"(c3)
        : "r"(a0), "r"(a1), "r"(a2), "r"(a3), "r"(b0), "r"(b1));
}
#define MBARRIER_INIT(addr, cnt) \
    asm volatile("mbarrier.init.shared.b64 [%0], %1;" :: "r"(addr), "r"(cnt) : "memory")
__device__ __forceinline__ void mbar_expect(uint32_t mbar, uint32_t bytes) {
    asm volatile("mbarrier.arrive.expect_tx.shared.b64 _, [%0], %1;"
                 :: "r"(mbar), "r"(bytes) : "memory");
}
__device__ __forceinline__ void bulk_g2s(uint32_t dst, const void* src, uint32_t bytes,
                                         uint32_t mbar) {
    asm volatile("cp.async.bulk.shared::cta.global.mbarrier::complete_tx::bytes "
                 "[%0], [%1], %2, [%3];"
                 :: "r"(dst), "l"(src), "r"(bytes), "r"(mbar) : "memory");
}
__device__ __forceinline__ void mbar_wait(uint32_t mbar, uint32_t parity) {
    uint32_t done;
    asm volatile(
        "{ .reg .pred p; mbarrier.try_wait.parity.acquire.cta.shared::cta.b64 p, [%1], %2; selp.b32 %0, 1, 0, p; }"
        : "=r"(done) : "r"(mbar), "r"(parity) : "memory");
    if (!done) {
        asm volatile(
            "{ .reg .pred P1;\n"
            "WAIT_LOOP_%=:\n"
            "mbarrier.try_wait.parity.acquire.cta.shared::cta.b64 P1, [%0], %1, 0x989680;\n"
            "@P1 bra.uni WAIT_DONE_%=;\n"
            "bra.uni WAIT_LOOP_%=;\n"
            "WAIT_DONE_%=:\n}"
            :: "r"(mbar), "r"(parity) : "memory");
    }
}

// ---------------- init ------------------------------------------------------
__global__ void init_kernel() {
    int i = blockIdx.x * blockDim.x + threadIdx.x;
    if (i < NE) { g_cnt[i] = 0; g_cur[i] = 0; }
    if (i < ROWS_MAX) g_row_tok[i] = 0;
}

// ---------------- router ----------------------------------------------------
__global__ void router_kernel(const float* __restrict__ x,
                              const float* __restrict__ rw,
                              const float* __restrict__ rb) {
    int gtid = blockIdx.x * blockDim.x + threadIdx.x;
    int t = gtid >> 5, lane = gtid & 31;
    if (t >= T_TOK) return;
    const float* xr = x + (size_t)t * DMODEL;
    float acc[NE];
#pragma unroll
    for (int e = 0; e < NE; e++) acc[e] = 0.f;
    for (int d = lane; d < DMODEL; d += 32) {
        float xv = xr[d];
        const float* r = rw + d * NE;
#pragma unroll
        for (int e = 0; e < NE; e++) acc[e] = fmaf(xv, r[e], acc[e]);
    }
#pragma unroll
    for (int off = 16; off > 0; off >>= 1)
#pragma unroll
        for (int e = 0; e < NE; e++)
            acc[e] += __shfl_down_sync(0xffffffffu, acc[e], off);
    if (lane == 0) {
        float best = -1e30f, second = -1e30f;
        int b0 = 0, b1 = 0;
#pragma unroll
        for (int e = 0; e < NE; e++) {
            float l = acc[e] + rb[e];
            if (l > best)        { second = best; b1 = b0; best = l; b0 = e; }
            else if (l > second) { second = l; b1 = e; }
        }
        float w0 = 1.f / (1.f + __expf(second - best));
        g_tok_e[2*t+0] = b0;  g_tok_w[2*t+0] = w0;
        g_tok_e[2*t+1] = b1;  g_tok_w[2*t+1] = 1.f - w0;
        atomicAdd(&g_cnt[b0], 1);
        atomicAdd(&g_cnt[b1], 1);
    }
}

// ---------------- offsets ---------------------------------------------------
__global__ void offsets_kernel() {
    int o = 0;
    for (int e = 0; e < NE; e++) {
        g_pofs[e] = o;
        o += ((g_cnt[e] + BM - 1) / BM) * BM;
    }
    g_pofs[NE] = o;
}

// ---------------- scatter ---------------------------------------------------
__global__ void scatter_kernel() {
    int t = blockIdx.x * blockDim.x + threadIdx.x;
    if (t >= T_TOK) return;
#pragma unroll
    for (int k = 0; k < TOPK; k++) {
        int e = g_tok_e[2*t+k];
        int pos = g_pofs[e] + atomicAdd(&g_cur[e], 1);
        g_row_tok[pos] = t;
        g_tok_slot[2*t+k] = pos;
    }
}

// ---------------- gather x -> fp16 tiled-swizzled ---------------------------
__global__ void gather_h_kernel(const float* __restrict__ x) {
    int id = blockIdx.x * blockDim.x + threadIdx.x;
    const int UNITS = DMODEL / 8;                      // 64
    if (id >= ROWS_MAX * UNITS) return;
    int s  = id / UNITS;
    int un = id % UNITS;
    int kch = un >> 3;
    int u   = un & 7;
    int r   = s & (BM - 1);
    int tok = g_row_tok[s];
    const float4* src = (const float4*)(x + (size_t)tok * DMODEL + un * 8);
    float4 v0 = src[0], v1 = src[1];
    __half2 h[4];
    h[0] = __floats2half2_rn(v0.x, v0.y);
    h[1] = __floats2half2_rn(v0.z, v0.w);
    h[2] = __floats2half2_rn(v1.x, v1.y);
    h[3] = __floats2half2_rn(v1.z, v1.w);
    size_t base = ((size_t)(s >> 7) * (DMODEL / 64) + kch) * 8192;
    *(uint4*)((__half*)g_xg + base + r * 64 + ((u ^ (r & 7)) << 3)) = *(uint4*)h;
}

// ---------------- weight transpose -> fp16 tiled-swizzled -------------------
__global__ void transpose_h_kernel(const float* __restrict__ src, __half* __restrict__ dst,
                                   int R, int C) {
    __shared__ float tile[32][33];
    int e = blockIdx.z;
    int c0 = blockIdx.x * 32, r0 = blockIdx.y * 32;   // c=n, r=k
    const float* s = src + (size_t)e * R * C;
    for (int kk = threadIdx.y; kk < 32; kk += 4)
        tile[kk][threadIdx.x] = s[(size_t)(r0 + kk) * C + c0 + threadIdx.x];
    __syncthreads();
    int n  = c0 + threadIdx.x;
    int kg = threadIdx.y;
    int kbase = r0 + kg * 8;
    __half2 h[4];
#pragma unroll
    for (int j = 0; j < 4; j++)
        h[j] = __floats2half2_rn(tile[kg * 8 + 2*j][threadIdx.x],
                                 tile[kg * 8 + 2*j + 1][threadIdx.x]);
    int nn = n & 255;
    int u  = (kbase & 63) >> 3;
    size_t base = (((size_t)e * (C >> 8) + (n >> 8)) * (R >> 6) + (kbase >> 6)) * 16384;
    *(uint4*)(dst + base + nn * 64 + ((u ^ (nn & 7)) << 3)) = *(uint4*)h;
}

// ---------------- grouped fp16 mma.sync GEMM, 4-stage bulk pipeline ---------
// (R10 structure: per-iter __syncthreads; producer never blocks on consumers)
#define A_STAGE 16384
#define B_STAGE 32768
#define STAGE_BYTES (A_STAGE + B_STAGE)            // 49152
#define NSTAGE 4
#define SM_MB (NSTAGE * STAGE_BYTES)               // 196608
#define SMEM_TOTAL (SM_MB + 64)

template<int KD, int NTOT, bool TILED_OUT>
__global__ __launch_bounds__(256, 1)
void ffn_mma(const __half* __restrict__ Atiled,
             const __half* __restrict__ Wt,
             const float* __restrict__ bias,
             void* __restrict__ OutV) {
    extern __shared__ __align__(128) char smem[];
    const int tid  = threadIdx.x;
    const int wid  = tid >> 5;
    const int lane = tid & 31;
    const int qid  = lane >> 2;
    const int rid  = lane & 3;
    const int wm   = wid >> 2;
    const int wn   = wid & 3;

    const int r0 = blockIdx.x * BM;
    if (r0 >= g_pofs[NE]) return;
    int e = 0;
    while (r0 >= g_pofs[e + 1]) e++;

    const uint32_t sb = smem_u32(smem);
    if (tid == 0) {
#pragma unroll
        for (int s = 0; s < NSTAGE; s++)
            MBARRIER_INIT(sb + SM_MB + 8 * s, 1);
    }
    __syncthreads();

    const int NCH = KD / 64;
    const __half* Asrc = Atiled + (size_t)blockIdx.x * NCH * 8192;
    const __half* Bsrc = Wt + (((size_t)e * (NTOT / 256) + blockIdx.y) * NCH) * 16384;
    const int n0 = blockIdx.y * BN;

    const int sel = lane >> 3, lr = lane & 7;
    uint32_t a_base[4], a_s7[4];
#pragma unroll
    for (int mt = 0; mt < 4; mt++) {
        int arow = wm * 64 + mt * 16 + (sel & 1) * 8 + lr;
        a_base[mt] = (uint32_t)(arow * 128);
        a_s7[mt]   = (uint32_t)(arow & 7);
    }
    const uint32_t ua0 = (uint32_t)(sel >> 1);
    uint32_t b_base[4], b_s7[4];
#pragma unroll
    for (int g = 0; g < 4; g++) {
        int brow = wn * 64 + (2 * g + (sel >> 1)) * 8 + lr;
        b_base[g] = (uint32_t)(A_STAGE + brow * 128);
        b_s7[g]   = (uint32_t)(brow & 7);
    }
    const uint32_t ub0 = (uint32_t)(sel & 1);

    float acc[4][8][4];
#pragma unroll
    for (int i = 0; i < 4; i++)
#pragma unroll
        for (int j = 0; j < 8; j++)
#pragma unroll
            for (int k = 0; k < 4; k++) acc[i][j][k] = 0.f;

    const int NIT = NCH;
    const int PRO = (NIT < NSTAGE - 1) ? NIT : NSTAGE - 1;   // 3 in-flight

    if (tid == 0) {
        for (int s = 0; s < PRO; s++) {
            mbar_expect(sb + SM_MB + 8 * s, STAGE_BYTES);
            bulk_g2s(sb + s * STAGE_BYTES,           Asrc + (size_t)s * 8192,  A_STAGE,
                     sb + SM_MB + 8 * s);
            bulk_g2s(sb + s * STAGE_BYTES + A_STAGE, Bsrc + (size_t)s * 16384, B_STAGE,
                     sb + SM_MB + 8 * s);
        }
    }

    for (int it = 0; it < NIT; it++) {
        int stage = it % NSTAGE;
        if (it + PRO < NIT && tid == 0) {
            int s2 = (it + PRO) % NSTAGE;
            mbar_expect(sb + SM_MB + 8 * s2, STAGE_BYTES);
            bulk_g2s(sb + s2 * STAGE_BYTES,           Asrc + (size_t)(it + PRO) * 8192,  A_STAGE,
                     sb + SM_MB + 8 * s2);
            bulk_g2s(sb + s2 * STAGE_BYTES + A_STAGE, Bsrc + (size_t)(it + PRO) * 16384, B_STAGE,
                     sb + SM_MB + 8 * s2);
        }
        mbar_wait(sb + SM_MB + 8 * stage, (it / NSTAGE) & 1);

        const uint32_t sbS = sb + stage * STAGE_BYTES;
#pragma unroll
        for (int ks = 0; ks < 4; ks++) {
            uint32_t a[4][4], b[8][2];
#pragma unroll
            for (int mt = 0; mt < 4; mt++)
                ldsm_x4(a[mt][0], a[mt][1], a[mt][2], a[mt][3],
                        sbS + a_base[mt] + (((ua0 + 2 * ks) ^ a_s7[mt]) << 4));
#pragma unroll
            for (int g = 0; g < 4; g++)
                ldsm_x4(b[2*g][0], b[2*g][1], b[2*g+1][0], b[2*g+1][1],
                        sbS + b_base[g] + (((ub0 + 2 * ks) ^ b_s7[g]) << 4));
#pragma unroll
            for (int mt = 0; mt < 4; mt++)
#pragma unroll
                for (int nt = 0; nt < 8; nt++)
                    mma_f16(acc[mt][nt][0], acc[mt][nt][1], acc[mt][nt][2], acc[mt][nt][3],
                            a[mt][0], a[mt][1], a[mt][2], a[mt][3],
                            b[nt][0], b[nt][1]);
        }
        __syncthreads();
    }

    const float* be = bias + (size_t)e * NTOT + n0;
    if (TILED_OUT) {
        // relu + fp16; stage tile in smem in exact gmem-tiled-swizzled order,
        // then fully coalesced linear copy-out. (stage smem is free after the
        // loop-end __syncthreads.)
        __half* st = (__half*)smem;
#pragma unroll
        for (int mt = 0; mt < 4; mt++) {
            int r0l = wm * 64 + mt * 16 + qid;
            int r1l = r0l + 8;
#pragma unroll
            for (int nt = 0; nt < 8; nt++) {
                int col = wn * 64 + nt * 8 + 2 * rid;
                float2 bv = *(const float2*)(be + col);
                __half2 h0 = __floats2half2_rn(fmaxf(acc[mt][nt][0] + bv.x, 0.f),
                                               fmaxf(acc[mt][nt][1] + bv.y, 0.f));
                __half2 h1 = __floats2half2_rn(fmaxf(acc[mt][nt][2] + bv.x, 0.f),
                                               fmaxf(acc[mt][nt][3] + bv.y, 0.f));
                int base_c = wn * 8192;   // 64-col chunk index == wn
                *(__half2*)(st + base_c + r0l * 64 + ((nt ^ (r0l & 7)) << 3) + 2 * rid) = h0;
                *(__half2*)(st + base_c + r1l * 64 + ((nt ^ (r1l & 7)) << 3) + 2 * rid) = h1;
            }
        }
        __syncthreads();
        __half* Out = (__half*)OutV;
        size_t gbase = ((size_t)blockIdx.x * (NTOT >> 6) + (n0 >> 6)) * 8192;
        uint4* gdst = (uint4*)(Out + gbase);
        const uint4* ssrc = (const uint4*)st;
#pragma unroll
        for (int i = 0; i < 16; i++)
            gdst[tid + i * 256] = ssrc[tid + i * 256];
    } else {
#pragma unroll
        for (int mt = 0; mt < 4; mt++) {
            int rowl = wm * 64 + mt * 16 + qid;
#pragma unroll
            for (int nt = 0; nt < 8; nt++) {
                int col = wn * 64 + nt * 8 + 2 * rid;
                float2 bv = *(const float2*)(be + col);
                float2 v0, v1;
                v0.x = acc[mt][nt][0] + bv.x;
                v0.y = acc[mt][nt][1] + bv.y;
                v1.x = acc[mt][nt][2] + bv.x;
                v1.y = acc[mt][nt][3] + bv.y;
                float* Out = (float*)OutV;
                int row = r0 + rowl;
                *(float2*)(Out + (size_t)row * NTOT + n0 + col)       = v0;
                *(float2*)(Out + (size_t)(row + 8) * NTOT + n0 + col) = v1;
            }
        }
    }
}

// ---------------- combine ---------------------------------------------------
__global__ void combine_kernel(float* __restrict__ out) {
    int gid = blockIdx.x * blockDim.x + threadIdx.x;
    int t = gid >> 7;
    int j = (gid & 127) * 4;
    if (t >= T_TOK) return;
    int s0 = g_tok_slot[2*t], s1 = g_tok_slot[2*t+1];
    float w0 = g_tok_w[2*t], w1 = g_tok_w[2*t+1];
    float4 a = *(const float4*)(g_eout + (size_t)s0 * DMODEL + j);
    float4 b = *(const float4*)(g_eout + (size_t)s1 * DMODEL + j);
    float4 o;
    o.x = w0 * a.x + w1 * b.x;
    o.y = w0 * a.y + w1 * b.y;
    o.z = w0 * a.z + w1 * b.z;
    o.w = w0 * a.w + w1 * b.w;
    *(float4*)(out + (size_t)t * DMODEL + j) = o;
}

// ---------------------------------------------------------------------------
extern "C" void kernel_launch(void* const* d_in, const int* in_sizes, int n_in,
                              void* d_out, int out_size) {
    const float* x        = (const float*)d_in[0];
    const float* router_w = (const float*)d_in[1];
    const float* router_b = (const float*)d_in[2];
    const float* w1       = (const float*)d_in[3];
    const float* b1       = (const float*)d_in[4];
    const float* w2       = (const float*)d_in[5];
    const float* b2       = (const float*)d_in[6];
    float* out            = (float*)d_out;
    (void)in_sizes; (void)n_in; (void)out_size;

    __half* hid; cudaGetSymbolAddress((void**)&hid, g_hidden);
    float*  eo;  cudaGetSymbolAddress((void**)&eo,  g_eout);
    __half* xg;  cudaGetSymbolAddress((void**)&xg,  g_xg);
    __half* w1t; cudaGetSymbolAddress((void**)&w1t, g_w1t);
    __half* w2t; cudaGetSymbolAddress((void**)&w2t, g_w2t);

    cudaFuncSetAttribute(ffn_mma<DMODEL, FF, true >,
                         cudaFuncAttributeMaxDynamicSharedMemorySize, SMEM_TOTAL);
    cudaFuncSetAttribute(ffn_mma<FF, DMODEL, false>,
                         cudaFuncAttributeMaxDynamicSharedMemorySize, SMEM_TOTAL);

    init_kernel<<<(ROWS_MAX + 255) / 256, 256>>>();
    router_kernel<<<(T_TOK * 32 + 255) / 256, 256>>>(x, router_w, router_b);
    offsets_kernel<<<1, 1>>>();
    scatter_kernel<<<(T_TOK + 255) / 256, 256>>>();

    gather_h_kernel<<<(ROWS_MAX * (DMODEL / 8) + 255) / 256, 256>>>(x);
    transpose_h_kernel<<<dim3(FF/32, DMODEL/32, NE), dim3(32, 4)>>>(w1, w1t, DMODEL, FF);
    transpose_h_kernel<<<dim3(DMODEL/32, FF/32, NE), dim3(32, 4)>>>(w2, w2t, FF, DMODEL);

    dim3 g1(RTILES, FF / BN);       // 136 x 8
    ffn_mma<DMODEL, FF, true><<<g1, 256, SMEM_TOTAL>>>(xg, w1t, b1, hid);

    dim3 g2(RTILES, DMODEL / BN);   // 136 x 2
    ffn_mma<FF, DMODEL, false><<<g2, 256, SMEM_TOTAL>>>(hid, w2t, b2, eo);

    combine_kernel<<<(T_TOK * 128 + 255) / 256, 256>>>(out);
}

// round 13
// speedup vs baseline: 1.4089x; 1.0053x over previous
#include <cuda_runtime.h>
#include <cuda_fp16.h>
#include <cstdint>
#include <math.h>

#define T_TOK   8192
#define DMODEL  512
#define FF      2048
#define NE      8
#define TOPK    2

#define BM 128
#define BN 256
#define ROWS_MAX (TOPK*T_TOK + NE*BM)   // 17408
#define RTILES   (ROWS_MAX / BM)        // 136

// ---------------- static device scratch -------------------------------------
__device__ __half g_hidden[(size_t)ROWS_MAX * FF];    // [136][32][8192h]
__device__ float  g_eout[(size_t)ROWS_MAX * DMODEL];  // row-major fp32
__device__ __half g_xg[(size_t)ROWS_MAX * DMODEL];    // [136][8][8192h]
__device__ __half g_w1t[(size_t)NE * FF * DMODEL];    // tiled
__device__ __half g_w2t[(size_t)NE * DMODEL * FF];    // tiled
__device__ int   g_row_tok[ROWS_MAX];
__device__ int   g_tok_e[T_TOK * TOPK];
__device__ int   g_tok_slot[T_TOK * TOPK];
__device__ float g_tok_w[T_TOK * TOPK];
__device__ int   g_cnt[NE];
__device__ int   g_cur[NE];
__device__ int   g_pofs[NE + 1];

// ---------------- helpers ---------------------------------------------------
__device__ __forceinline__ uint32_t smem_u32(const void* p) {
    uint32_t a;
    asm("{ .reg .u64 t; cvta.to.shared.u64 t, %1; cvt.u32.u64 %0, t; }" : "=r"(a) : "l"(p));
    return a;
}
__device__ __forceinline__ void ldsm_x4(uint32_t& r0, uint32_t& r1, uint32_t& r2, uint32_t& r3,
                                        uint32_t addr) {
    asm volatile("ldmatrix.sync.aligned.m8n8.x4.shared.b16 {%0,%1,%2,%3}, [%4];"
                 : "=r"(r0), "=r"(r1), "=r"(r2), "=r"(r3) : "r"(addr));
}
__device__ __forceinline__ void mma_f16(float& c0, float& c1, float& c2, float& c3,
                                        uint32_t a0, uint32_t a1, uint32_t a2, uint32_t a3,
                                        uint32_t b0, uint32_t b1) {
    asm volatile(
        "mma.sync.aligned.m16n8k16.row.col.f32.f16.f16.f32 "
        "{%0,%1,%2,%3}, {%4,%5,%6,%7}, {%8,%9}, {%0,%1,%2,%3};"
        : "+f"(c0), "+f"(c1), "+f"(c2), "+f"(c3)
        : "r"(a0), "r"(a1), "r"(a2), "r"(a3), "r"(b0), "r"(b1));
}
#define MBARRIER_INIT(addr, cnt) \
    asm volatile("mbarrier.init.shared.b64 [%0], %1;" :: "r"(addr), "r"(cnt) : "memory")
__device__ __forceinline__ void mbar_expect(uint32_t mbar, uint32_t bytes) {
    asm volatile("mbarrier.arrive.expect_tx.shared.b64 _, [%0], %1;"
                 :: "r"(mbar), "r"(bytes) : "memory");
}
__device__ __forceinline__ void bulk_g2s(uint32_t dst, const void* src, uint32_t bytes,
                                         uint32_t mbar) {
    asm volatile("cp.async.bulk.shared::cta.global.mbarrier::complete_tx::bytes "
                 "[%0], [%1], %2, [%3];"
                 :: "r"(dst), "l"(src), "r"(bytes), "r"(mbar) : "memory");
}
__device__ __forceinline__ void mbar_wait(uint32_t mbar, uint32_t parity) {
    uint32_t done;
    asm volatile(
        "{ .reg .pred p; mbarrier.try_wait.parity.acquire.cta.shared::cta.b64 p, [%1], %2; selp.b32 %0, 1, 0, p; }"
        : "=r"(done) : "r"(mbar), "r"(parity) : "memory");
    if (!done) {
        asm volatile(
            "{ .reg .pred P1;\n"
            "WAIT_LOOP_%=:\n"
            "mbarrier.try_wait.parity.acquire.cta.shared::cta.b64 P1, [%0], %1, 0x989680;\n"
            "@P1 bra.uni WAIT_DONE_%=;\n"
            "bra.uni WAIT_LOOP_%=;\n"
            "WAIT_DONE_%=:\n}"
            :: "r"(mbar), "r"(parity) : "memory");
    }
}

// ---------------- init ------------------------------------------------------
__global__ void init_kernel() {
    int i = blockIdx.x * blockDim.x + threadIdx.x;
    if (i < NE) { g_cnt[i] = 0; g_cur[i] = 0; }
    if (i < ROWS_MAX) g_row_tok[i] = 0;
}

// ---------------- router ----------------------------------------------------
__global__ void router_kernel(const float* __restrict__ x,
                              const float* __restrict__ rw,
                              const float* __restrict__ rb) {
    int gtid = blockIdx.x * blockDim.x + threadIdx.x;
    int t = gtid >> 5, lane = gtid & 31;
    if (t >= T_TOK) return;
    const float* xr = x + (size_t)t * DMODEL;
    float acc[NE];
#pragma unroll
    for (int e = 0; e < NE; e++) acc[e] = 0.f;
    for (int d = lane; d < DMODEL; d += 32) {
        float xv = xr[d];
        const float* r = rw + d * NE;
#pragma unroll
        for (int e = 0; e < NE; e++) acc[e] = fmaf(xv, r[e], acc[e]);
    }
#pragma unroll
    for (int off = 16; off > 0; off >>= 1)
#pragma unroll
        for (int e = 0; e < NE; e++)
            acc[e] += __shfl_down_sync(0xffffffffu, acc[e], off);
    if (lane == 0) {
        float best = -1e30f, second = -1e30f;
        int b0 = 0, b1 = 0;
#pragma unroll
        for (int e = 0; e < NE; e++) {
            float l = acc[e] + rb[e];
            if (l > best)        { second = best; b1 = b0; best = l; b0 = e; }
            else if (l > second) { second = l; b1 = e; }
        }
        float w0 = 1.f / (1.f + __expf(second - best));
        g_tok_e[2*t+0] = b0;  g_tok_w[2*t+0] = w0;
        g_tok_e[2*t+1] = b1;  g_tok_w[2*t+1] = 1.f - w0;
        atomicAdd(&g_cnt[b0], 1);
        atomicAdd(&g_cnt[b1], 1);
    }
}

// ---------------- offsets ---------------------------------------------------
__global__ void offsets_kernel() {
    int o = 0;
    for (int e = 0; e < NE; e++) {
        g_pofs[e] = o;
        o += ((g_cnt[e] + BM - 1) / BM) * BM;
    }
    g_pofs[NE] = o;
}

// ---------------- scatter ---------------------------------------------------
__global__ void scatter_kernel() {
    int t = blockIdx.x * blockDim.x + threadIdx.x;
    if (t >= T_TOK) return;
#pragma unroll
    for (int k = 0; k < TOPK; k++) {
        int e = g_tok_e[2*t+k];
        int pos = g_pofs[e] + atomicAdd(&g_cur[e], 1);
        g_row_tok[pos] = t;
        g_tok_slot[2*t+k] = pos;
    }
}

// ---------------- gather x -> fp16 tiled-swizzled ---------------------------
__global__ void gather_h_kernel(const float* __restrict__ x) {
    int id = blockIdx.x * blockDim.x + threadIdx.x;
    const int UNITS = DMODEL / 8;                      // 64
    if (id >= ROWS_MAX * UNITS) return;
    int s  = id / UNITS;
    int un = id % UNITS;
    int kch = un >> 3;
    int u   = un & 7;
    int r   = s & (BM - 1);
    int tok = g_row_tok[s];
    const float4* src = (const float4*)(x + (size_t)tok * DMODEL + un * 8);
    float4 v0 = src[0], v1 = src[1];
    __half2 h[4];
    h[0] = __floats2half2_rn(v0.x, v0.y);
    h[1] = __floats2half2_rn(v0.z, v0.w);
    h[2] = __floats2half2_rn(v1.x, v1.y);
    h[3] = __floats2half2_rn(v1.z, v1.w);
    size_t base = ((size_t)(s >> 7) * (DMODEL / 64) + kch) * 8192;
    *(uint4*)((__half*)g_xg + base + r * 64 + ((u ^ (r & 7)) << 3)) = *(uint4*)h;
}

// ---------------- weight transpose -> fp16 tiled-swizzled -------------------
__global__ void transpose_h_kernel(const float* __restrict__ src, __half* __restrict__ dst,
                                   int R, int C) {
    __shared__ float tile[32][33];
    int e = blockIdx.z;
    int c0 = blockIdx.x * 32, r0 = blockIdx.y * 32;   // c=n, r=k
    const float* s = src + (size_t)e * R * C;
    for (int kk = threadIdx.y; kk < 32; kk += 4)
        tile[kk][threadIdx.x] = s[(size_t)(r0 + kk) * C + c0 + threadIdx.x];
    __syncthreads();
    int n  = c0 + threadIdx.x;
    int kg = threadIdx.y;
    int kbase = r0 + kg * 8;
    __half2 h[4];
#pragma unroll
    for (int j = 0; j < 4; j++)
        h[j] = __floats2half2_rn(tile[kg * 8 + 2*j][threadIdx.x],
                                 tile[kg * 8 + 2*j + 1][threadIdx.x]);
    int nn = n & 255;
    int u  = (kbase & 63) >> 3;
    size_t base = (((size_t)e * (C >> 8) + (n >> 8)) * (R >> 6) + (kbase >> 6)) * 16384;
    *(uint4*)(dst + base + nn * 64 + ((u ^ (nn & 7)) << 3)) = *(uint4*)h;
}

// ---------------- grouped fp16 mma.sync GEMM, 4-stage bulk pipeline ---------
// R12 structure + software-pipelined (double-buffered) fragments in the ks loop.
#define A_STAGE 16384
#define B_STAGE 32768
#define STAGE_BYTES (A_STAGE + B_STAGE)            // 49152
#define NSTAGE 4
#define SM_MB (NSTAGE * STAGE_BYTES)               // 196608
#define SMEM_TOTAL (SM_MB + 64)

template<int KD, int NTOT, bool TILED_OUT>
__global__ __launch_bounds__(256, 1)
void ffn_mma(const __half* __restrict__ Atiled,
             const __half* __restrict__ Wt,
             const float* __restrict__ bias,
             void* __restrict__ OutV) {
    extern __shared__ __align__(128) char smem[];
    const int tid  = threadIdx.x;
    const int wid  = tid >> 5;
    const int lane = tid & 31;
    const int qid  = lane >> 2;
    const int rid  = lane & 3;
    const int wm   = wid >> 2;
    const int wn   = wid & 3;

    const int r0 = blockIdx.x * BM;
    if (r0 >= g_pofs[NE]) return;
    int e = 0;
    while (r0 >= g_pofs[e + 1]) e++;

    const uint32_t sb = smem_u32(smem);
    if (tid == 0) {
#pragma unroll
        for (int s = 0; s < NSTAGE; s++)
            MBARRIER_INIT(sb + SM_MB + 8 * s, 1);
    }
    __syncthreads();

    const int NCH = KD / 64;
    const __half* Asrc = Atiled + (size_t)blockIdx.x * NCH * 8192;
    const __half* Bsrc = Wt + (((size_t)e * (NTOT / 256) + blockIdx.y) * NCH) * 16384;
    const int n0 = blockIdx.y * BN;

    const int sel = lane >> 3, lr = lane & 7;
    uint32_t a_base[4], a_s7[4];
#pragma unroll
    for (int mt = 0; mt < 4; mt++) {
        int arow = wm * 64 + mt * 16 + (sel & 1) * 8 + lr;
        a_base[mt] = (uint32_t)(arow * 128);
        a_s7[mt]   = (uint32_t)(arow & 7);
    }
    const uint32_t ua0 = (uint32_t)(sel >> 1);
    uint32_t b_base[4], b_s7[4];
#pragma unroll
    for (int g = 0; g < 4; g++) {
        int brow = wn * 64 + (2 * g + (sel >> 1)) * 8 + lr;
        b_base[g] = (uint32_t)(A_STAGE + brow * 128);
        b_s7[g]   = (uint32_t)(brow & 7);
    }
    const uint32_t ub0 = (uint32_t)(sel & 1);

    float acc[4][8][4];
#pragma unroll
    for (int i = 0; i < 4; i++)
#pragma unroll
        for (int j = 0; j < 8; j++)
#pragma unroll
            for (int k = 0; k < 4; k++) acc[i][j][k] = 0.f;

    const int NIT = NCH;
    const int PRO = (NIT < NSTAGE - 1) ? NIT : NSTAGE - 1;   // 3 in-flight

    if (tid == 0) {
        for (int s = 0; s < PRO; s++) {
            mbar_expect(sb + SM_MB + 8 * s, STAGE_BYTES);
            bulk_g2s(sb + s * STAGE_BYTES,           Asrc + (size_t)s * 8192,  A_STAGE,
                     sb + SM_MB + 8 * s);
            bulk_g2s(sb + s * STAGE_BYTES + A_STAGE, Bsrc + (size_t)s * 16384, B_STAGE,
                     sb + SM_MB + 8 * s);
        }
    }

    // double-buffered fragments
    uint32_t a[2][4][4], b[2][8][2];

    for (int it = 0; it < NIT; it++) {
        int stage = it % NSTAGE;
        if (it + PRO < NIT && tid == 0) {
            int s2 = (it + PRO) % NSTAGE;
            mbar_expect(sb + SM_MB + 8 * s2, STAGE_BYTES);
            bulk_g2s(sb + s2 * STAGE_BYTES,           Asrc + (size_t)(it + PRO) * 8192,  A_STAGE,
                     sb + SM_MB + 8 * s2);
            bulk_g2s(sb + s2 * STAGE_BYTES + A_STAGE, Bsrc + (size_t)(it + PRO) * 16384, B_STAGE,
                     sb + SM_MB + 8 * s2);
        }
        mbar_wait(sb + SM_MB + 8 * stage, (it / NSTAGE) & 1);

        const uint32_t sbS = sb + stage * STAGE_BYTES;

        // prefetch ks=0 fragments
#pragma unroll
        for (int mt = 0; mt < 4; mt++)
            ldsm_x4(a[0][mt][0], a[0][mt][1], a[0][mt][2], a[0][mt][3],
                    sbS + a_base[mt] + ((ua0 ^ a_s7[mt]) << 4));
#pragma unroll
        for (int g = 0; g < 4; g++)
            ldsm_x4(b[0][2*g][0], b[0][2*g][1], b[0][2*g+1][0], b[0][2*g+1][1],
                    sbS + b_base[g] + ((ub0 ^ b_s7[g]) << 4));

#pragma unroll
        for (int ks = 0; ks < 4; ks++) {
            const int cur = ks & 1;
            if (ks < 3) {
                const int nxt = cur ^ 1;
#pragma unroll
                for (int mt = 0; mt < 4; mt++)
                    ldsm_x4(a[nxt][mt][0], a[nxt][mt][1], a[nxt][mt][2], a[nxt][mt][3],
                            sbS + a_base[mt] + (((ua0 + 2 * (ks + 1)) ^ a_s7[mt]) << 4));
#pragma unroll
                for (int g = 0; g < 4; g++)
                    ldsm_x4(b[nxt][2*g][0], b[nxt][2*g][1], b[nxt][2*g+1][0], b[nxt][2*g+1][1],
                            sbS + b_base[g] + (((ub0 + 2 * (ks + 1)) ^ b_s7[g]) << 4));
            }
#pragma unroll
            for (int mt = 0; mt < 4; mt++)
#pragma unroll
                for (int nt = 0; nt < 8; nt++)
                    mma_f16(acc[mt][nt][0], acc[mt][nt][1], acc[mt][nt][2], acc[mt][nt][3],
                            a[cur][mt][0], a[cur][mt][1], a[cur][mt][2], a[cur][mt][3],
                            b[cur][nt][0], b[cur][nt][1]);
        }
        __syncthreads();
    }

    const float* be = bias + (size_t)e * NTOT + n0;
    if (TILED_OUT) {
        // relu + fp16; stage tile in smem in gmem-tiled-swizzled order, then
        // fully coalesced linear copy-out.
        __half* st = (__half*)smem;
#pragma unroll
        for (int mt = 0; mt < 4; mt++) {
            int r0l = wm * 64 + mt * 16 + qid;
            int r1l = r0l + 8;
#pragma unroll
            for (int nt = 0; nt < 8; nt++) {
                int col = wn * 64 + nt * 8 + 2 * rid;
                float2 bv = *(const float2*)(be + col);
                __half2 h0 = __floats2half2_rn(fmaxf(acc[mt][nt][0] + bv.x, 0.f),
                                               fmaxf(acc[mt][nt][1] + bv.y, 0.f));
                __half2 h1 = __floats2half2_rn(fmaxf(acc[mt][nt][2] + bv.x, 0.f),
                                               fmaxf(acc[mt][nt][3] + bv.y, 0.f));
                int base_c = wn * 8192;
                *(__half2*)(st + base_c + r0l * 64 + ((nt ^ (r0l & 7)) << 3) + 2 * rid) = h0;
                *(__half2*)(st + base_c + r1l * 64 + ((nt ^ (r1l & 7)) << 3) + 2 * rid) = h1;
            }
        }
        __syncthreads();
        __half* Out = (__half*)OutV;
        size_t gbase = ((size_t)blockIdx.x * (NTOT >> 6) + (n0 >> 6)) * 8192;
        uint4* gdst = (uint4*)(Out + gbase);
        const uint4* ssrc = (const uint4*)st;
#pragma unroll
        for (int i = 0; i < 16; i++)
            gdst[tid + i * 256] = ssrc[tid + i * 256];
    } else {
#pragma unroll
        for (int mt = 0; mt < 4; mt++) {
            int rowl = wm * 64 + mt * 16 + qid;
#pragma unroll
            for (int nt = 0; nt < 8; nt++) {
                int col = wn * 64 + nt * 8 + 2 * rid;
                float2 bv = *(const float2*)(be + col);
                float2 v0, v1;
                v0.x = acc[mt][nt][0] + bv.x;
                v0.y = acc[mt][nt][1] + bv.y;
                v1.x = acc[mt][nt][2] + bv.x;
                v1.y = acc[mt][nt][3] + bv.y;
                float* Out = (float*)OutV;
                int row = r0 + rowl;
                *(float2*)(Out + (size_t)row * NTOT + n0 + col)       = v0;
                *(float2*)(Out + (size_t)(row + 8) * NTOT + n0 + col) = v1;
            }
        }
    }
}

// ---------------- combine ---------------------------------------------------
__global__ void combine_kernel(float* __restrict__ out) {
    int gid = blockIdx.x * blockDim.x + threadIdx.x;
    int t = gid >> 7;
    int j = (gid & 127) * 4;
    if (t >= T_TOK) return;
    int s0 = g_tok_slot[2*t], s1 = g_tok_slot[2*t+1];
    float w0 = g_tok_w[2*t], w1 = g_tok_w[2*t+1];
    float4 a = *(const float4*)(g_eout + (size_t)s0 * DMODEL + j);
    float4 b = *(const float4*)(g_eout + (size_t)s1 * DMODEL + j);
    float4 o;
    o.x = w0 * a.x + w1 * b.x;
    o.y = w0 * a.y + w1 * b.y;
    o.z = w0 * a.z + w1 * b.z;
    o.w = w0 * a.w + w1 * b.w;
    *(float4*)(out + (size_t)t * DMODEL + j) = o;
}

// ---------------------------------------------------------------------------
extern "C" void kernel_launch(void* const* d_in, const int* in_sizes, int n_in,
                              void* d_out, int out_size) {
    const float* x        = (const float*)d_in[0];
    const float* router_w = (const float*)d_in[1];
    const float* router_b = (const float*)d_in[2];
    const float* w1       = (const float*)d_in[3];
    const float* b1       = (const float*)d_in[4];
    const float* w2       = (const float*)d_in[5];
    const float* b2       = (const float*)d_in[6];
    float* out            = (float*)d_out;
    (void)in_sizes; (void)n_in; (void)out_size;

    __half* hid; cudaGetSymbolAddress((void**)&hid, g_hidden);
    float*  eo;  cudaGetSymbolAddress((void**)&eo,  g_eout);
    __half* xg;  cudaGetSymbolAddress((void**)&xg,  g_xg);
    __half* w1t; cudaGetSymbolAddress((void**)&w1t, g_w1t);
    __half* w2t; cudaGetSymbolAddress((void**)&w2t, g_w2t);

    cudaFuncSetAttribute(ffn_mma<DMODEL, FF, true >,
                         cudaFuncAttributeMaxDynamicSharedMemorySize, SMEM_TOTAL);
    cudaFuncSetAttribute(ffn_mma<FF, DMODEL, false>,
                         cudaFuncAttributeMaxDynamicSharedMemorySize, SMEM_TOTAL);

    init_kernel<<<(ROWS_MAX + 255) / 256, 256>>>();
    router_kernel<<<(T_TOK * 32 + 255) / 256, 256>>>(x, router_w, router_b);
    offsets_kernel<<<1, 1>>>();
    scatter_kernel<<<(T_TOK + 255) / 256, 256>>>();

    gather_h_kernel<<<(ROWS_MAX * (DMODEL / 8) + 255) / 256, 256>>>(x);
    transpose_h_kernel<<<dim3(FF/32, DMODEL/32, NE), dim3(32, 4)>>>(w1, w1t, DMODEL, FF);
    transpose_h_kernel<<<dim3(DMODEL/32, FF/32, NE), dim3(32, 4)>>>(w2, w2t, FF, DMODEL);

    dim3 g1(RTILES, FF / BN);       // 136 x 8
    ffn_mma<DMODEL, FF, true><<<g1, 256, SMEM_TOTAL>>>(xg, w1t, b1, hid);

    dim3 g2(RTILES, DMODEL / BN);   // 136 x 2
    ffn_mma<FF, DMODEL, false><<<g2, 256, SMEM_TOTAL>>>(hid, w2t, b2, eo);

    combine_kernel<<<(T_TOK * 128 + 255) / 256, 256>>>(out);
}